// round 8
// baseline (speedup 1.0000x reference)
#include <cuda_runtime.h>
#include <stdint.h>

// Problem constants
#define B 64
#define H 256
#define W 256
#define T 1000
#define TPAD 1024                      // alignment padding only
#define NROWS (B * H)                  // 16384 rows (b,h)
#define ROWPAIRS (NROWS / 2)           // 8192: block handles 2 rows per iteration
#define TOTAL_OUT ((double)B * H * T)  // 16,384,000 elements in the MSE mean
#define GRID 1064                      // 7 blocks/SM * 152 SMs (smem-limited: 32KB/block)

__global__ void zero_scalar_kernel(float* out) {
    if (threadIdx.x == 0 && blockIdx.x == 0) out[0] = 0.0f;
}

__device__ __forceinline__ int quantize(float x) {
    int q = (int)(x * 1000.0f) - 1;    // trunc == jnp astype(int32)
    if (q < 0) q += T;                 // floor-mod: only -1 -> 999 possible
    return q;
}

// Persistent blocks; each iteration processes TWO consecutive rows:
// threads 0-127 -> row 2rp (cols 2t,2t+1), threads 128-255 -> row 2rp+1,
// each half scattering into its own bin set. float2 global loads (rows are
// contiguous), tagged bins ((iter<<8)|w -- monotone, no re-init),
// double-buffered, ONE barrier per TWO rows.
//
// Per element, sum decomposition (see R6):
//  * squared terms telescope from atomicMax return values (stale tag -> 0),
//  * cross term: A-winner of a bin reads the int2 once, contributes -2*w*b.
__global__ __launch_bounds__(256, 7)
void holo_mse_kernel(const float* __restrict__ rec,
                     const float* __restrict__ tgt,
                     float* __restrict__ out)
{
    __shared__ int2 bins[2][2][TPAD];  // [buffer][row-half][bin]  (32 KB)
    __shared__ float warp_sums[8];

    const int t    = threadIdx.x;
    const int half = t >> 7;           // which of the 2 rows this thread feeds
    const int w0   = (t & 127) * 2;    // first of this thread's two columns
    const int w1   = w0 + 1;

    // one-time zero init (tag 0; iter starts at 1 so it never matches)
    #pragma unroll
    for (int i = t; i < 2 * TPAD; i += 256) {
        bins[0][0][i] = make_int2(0, 0);   // flat across [half][bin]
        bins[1][0][i] = make_int2(0, 0);
    }
    __syncthreads();

    float acc = 0.0f;
    int iter = 1;

    // preload first row-pair (float2: this thread's two columns of its row)
    int rp = blockIdx.x;
    float2 va = *(const float2*)(rec + (size_t)rp * 512 + 2 * t);
    float2 vb = *(const float2*)(tgt + (size_t)rp * 512 + 2 * t);

    for (; rp < ROWPAIRS; rp += GRID, ++iter) {
        const int p    = iter & 1;
        const int hi   = iter << 8;
        const int tag0 = hi | w0;
        const int tag1 = hi | w1;
        int2* __restrict__ bs = bins[p][half];

        int srow = 0;
        int qa0 = -1, qa1 = -1;

        // ---- element 0 (column w0) ----
        if (va.x != 0.0f) {
            qa0 = quantize(va.x);
            int old = atomicMax(&bs[qa0].x, tag0);
            if (tag0 > old) {
                unsigned pw = (unsigned)(old - hi);
                int pv = (pw < 256u) ? (int)pw : 0;
                srow += w0 * w0 - pv * pv;
            }
        }
        if (vb.x != 0.0f) {
            int qb = quantize(vb.x);
            int old = atomicMax(&bs[qb].y, tag0);
            if (tag0 > old) {
                unsigned pw = (unsigned)(old - hi);
                int pv = (pw < 256u) ? (int)pw : 0;
                srow += w0 * w0 - pv * pv;
            }
        }
        // ---- element 1 (column w1) ----
        if (va.y != 0.0f) {
            qa1 = quantize(va.y);
            int old = atomicMax(&bs[qa1].x, tag1);
            if (tag1 > old) {
                unsigned pw = (unsigned)(old - hi);
                int pv = (pw < 256u) ? (int)pw : 0;
                srow += w1 * w1 - pv * pv;
            }
        }
        if (vb.y != 0.0f) {
            int qb = quantize(vb.y);
            int old = atomicMax(&bs[qb].y, tag1);
            if (tag1 > old) {
                unsigned pw = (unsigned)(old - hi);
                int pv = (pw < 256u) ? (int)pw : 0;
                srow += w1 * w1 - pv * pv;
            }
        }

        // prefetch next row-pair (hidden behind barrier + cross-term phase)
        const int nrp = rp + GRID;
        if (nrp < ROWPAIRS) {
            va = *(const float2*)(rec + (size_t)nrp * 512 + 2 * t);
            vb = *(const float2*)(tgt + (size_t)nrp * 512 + 2 * t);
        }

        __syncthreads();               // atomics visible; also fences buffer reuse

        // cross terms: A-winner reads the pair once
        if (qa0 >= 0) {
            int2 v = bs[qa0];
            if (v.x == tag0) {
                unsigned db = (unsigned)(v.y - hi);
                int bq = (db < 256u) ? (int)db : 0;
                srow -= 2 * w0 * bq;
            }
        }
        if (qa1 >= 0) {
            int2 v = bs[qa1];
            if (v.x == tag1) {
                unsigned db = (unsigned)(v.y - hi);
                int bq = (db < 256u) ? (int)db : 0;
                srow -= 2 * w1 * bq;
            }
        }
        acc += (float)srow;            // |srow| < 2^20, ~8 iters: fp32-exact
    }

    // single block reduction at the end
    #pragma unroll
    for (int off = 16; off > 0; off >>= 1)
        acc += __shfl_down_sync(0xffffffffu, acc, off);
    if ((t & 31) == 0) warp_sums[t >> 5] = acc;
    __syncthreads();
    if (t < 32) {
        float v = (t < 8) ? warp_sums[t] : 0.0f;
        #pragma unroll
        for (int off = 4; off > 0; off >>= 1)
            v += __shfl_down_sync(0xffffffffu, v, off);
        if (t == 0)
            atomicAdd(out, v * (float)(1.0 / TOTAL_OUT));
    }
}

extern "C" void kernel_launch(void* const* d_in, const int* in_sizes, int n_in,
                              void* d_out, int out_size)
{
    const float* rec = (const float*)d_in[0];
    const float* tgt = (const float*)d_in[1];
    float* out = (float*)d_out;

    zero_scalar_kernel<<<1, 32>>>(out);
    holo_mse_kernel<<<GRID, 256>>>(rec, tgt, out);
}

// round 9
// speedup vs baseline: 1.1364x; 1.1364x over previous
#include <cuda_runtime.h>
#include <stdint.h>

// Problem constants
#define B 64
#define H 256
#define W 256
#define T 1000
#define TPAD 1024                      // alignment padding only
#define NROWS (B * H)                  // 16384 rows (b,h)
#define ROWPAIRS (NROWS / 2)           // 8192: block handles 2 rows per iteration
#define TOTAL_OUT ((double)B * H * T)  // 16,384,000 elements in the MSE mean
#define GRID 1216                      // 8 blocks/SM * 152 SMs

__global__ void zero_scalar_kernel(float* out) {
    if (threadIdx.x == 0 && blockIdx.x == 0) out[0] = 0.0f;
}

__device__ __forceinline__ int quantize(float x) {
    int q = (int)(x * 1000.0f) - 1;    // trunc == jnp astype(int32)
    if (q < 0) q += T;                 // floor-mod: only -1 -> 999 possible
    return q;
}

// Persistent blocks; each iteration processes TWO consecutive rows:
// threads 0-127 -> row 2rp (cols 2t,2t+1), threads 128-255 -> row 2rp+1,
// each half scattering into its own bin set. float2 global loads (rows are
// contiguous). Tagged bins ((iter<<8)|w -- monotone, so no re-init ever).
// SINGLE buffer (16 KB -> 8 blocks/SM) with TWO barriers per iteration:
//   barrier A: atomics visible before cross-term reads
//   barrier B: reads done before next iteration's (higher-tag) atomics
// Same barriers-per-row as R6, but half the LDGs/loop overhead and 2x ILP.
//
// Per element, sum decomposition:
//  * squared terms telescope from atomicMax RETURN values (stale tag -> 0),
//  * cross term: A-winner of a bin reads the int2 once, contributes -2*w*b.
__global__ __launch_bounds__(256, 8)
void holo_mse_kernel(const float* __restrict__ rec,
                     const float* __restrict__ tgt,
                     float* __restrict__ out)
{
    __shared__ int2 bins[2][TPAD];     // [row-half][bin]  (16 KB)
    __shared__ float warp_sums[8];

    const int t    = threadIdx.x;
    const int half = t >> 7;           // which of the 2 rows this thread feeds
    const int w0   = (t & 127) * 2;    // first of this thread's two columns
    const int w1   = w0 + 1;
    int2* __restrict__ bs = bins[half];

    // one-time zero init (tag 0; iter starts at 1 so it never matches)
    #pragma unroll
    for (int i = t; i < 2 * TPAD; i += 256)
        bins[0][i] = make_int2(0, 0);  // flat across [half][bin]
    __syncthreads();

    float acc = 0.0f;
    int iter = 1;

    // preload first row-pair (float2: this thread's two columns of its row)
    int rp = blockIdx.x;
    float2 va = *(const float2*)(rec + (size_t)rp * 512 + 2 * t);
    float2 vb = *(const float2*)(tgt + (size_t)rp * 512 + 2 * t);

    for (; rp < ROWPAIRS; rp += GRID, ++iter) {
        const int hi   = iter << 8;
        const int tag0 = hi | w0;
        const int tag1 = hi | w1;

        int srow = 0;
        int qa0 = -1, qa1 = -1;

        // ---- element 0 (column w0) ----
        if (va.x != 0.0f) {
            qa0 = quantize(va.x);
            int old = atomicMax(&bs[qa0].x, tag0);
            if (tag0 > old) {
                unsigned pw = (unsigned)(old - hi);
                int pv = (pw < 256u) ? (int)pw : 0;
                srow += w0 * w0 - pv * pv;
            }
        }
        if (vb.x != 0.0f) {
            int qb = quantize(vb.x);
            int old = atomicMax(&bs[qb].y, tag0);
            if (tag0 > old) {
                unsigned pw = (unsigned)(old - hi);
                int pv = (pw < 256u) ? (int)pw : 0;
                srow += w0 * w0 - pv * pv;
            }
        }
        // ---- element 1 (column w1) ----
        if (va.y != 0.0f) {
            qa1 = quantize(va.y);
            int old = atomicMax(&bs[qa1].x, tag1);
            if (tag1 > old) {
                unsigned pw = (unsigned)(old - hi);
                int pv = (pw < 256u) ? (int)pw : 0;
                srow += w1 * w1 - pv * pv;
            }
        }
        if (vb.y != 0.0f) {
            int qb = quantize(vb.y);
            int old = atomicMax(&bs[qb].y, tag1);
            if (tag1 > old) {
                unsigned pw = (unsigned)(old - hi);
                int pv = (pw < 256u) ? (int)pw : 0;
                srow += w1 * w1 - pv * pv;
            }
        }

        // prefetch next row-pair (overlaps barrier A + cross-term phase)
        const int nrp = rp + GRID;
        if (nrp < ROWPAIRS) {
            va = *(const float2*)(rec + (size_t)nrp * 512 + 2 * t);
            vb = *(const float2*)(tgt + (size_t)nrp * 512 + 2 * t);
        }

        __syncthreads();               // A: atomics visible to readers

        // cross terms: A-winner reads the pair once
        if (qa0 >= 0) {
            int2 v = bs[qa0];
            if (v.x == tag0) {
                unsigned db = (unsigned)(v.y - hi);
                int bq = (db < 256u) ? (int)db : 0;
                srow -= 2 * w0 * bq;
            }
        }
        if (qa1 >= 0) {
            int2 v = bs[qa1];
            if (v.x == tag1) {
                unsigned db = (unsigned)(v.y - hi);
                int bq = (db < 256u) ? (int)db : 0;
                srow -= 2 * w1 * bq;
            }
        }
        acc += (float)srow;            // |srow| < 2^20, ~7 iters: fp32-exact

        __syncthreads();               // B: reads done before next iter's atomics
    }

    // single block reduction at the end
    #pragma unroll
    for (int off = 16; off > 0; off >>= 1)
        acc += __shfl_down_sync(0xffffffffu, acc, off);
    if ((t & 31) == 0) warp_sums[t >> 5] = acc;
    __syncthreads();
    if (t < 32) {
        float v = (t < 8) ? warp_sums[t] : 0.0f;
        #pragma unroll
        for (int off = 4; off > 0; off >>= 1)
            v += __shfl_down_sync(0xffffffffu, v, off);
        if (t == 0)
            atomicAdd(out, v * (float)(1.0 / TOTAL_OUT));
    }
}

extern "C" void kernel_launch(void* const* d_in, const int* in_sizes, int n_in,
                              void* d_out, int out_size)
{
    const float* rec = (const float*)d_in[0];
    const float* tgt = (const float*)d_in[1];
    float* out = (float*)d_out;

    zero_scalar_kernel<<<1, 32>>>(out);
    holo_mse_kernel<<<GRID, 256>>>(rec, tgt, out);
}

// round 12
// speedup vs baseline: 1.1806x; 1.0388x over previous
#include <cuda_runtime.h>
#include <stdint.h>

#define B 64
#define H 256
#define W 256
#define T 1000
#define TPAD 1024
#define NROWS (B * H)
#define ROWPAIRS (NROWS / 2)
#define TOTAL_OUT ((double)B * H * T)
#define GRID 1216

__device__ float    g_partial = 0.0f;
__device__ unsigned g_count   = 0u;

__device__ __forceinline__ int quantize(float x) {
    int q = (int)(x * 1000.0f) - 1;    // trunc == jnp astype(int32)
    if (q < 0) q += T;                 // floor-mod: only -1 -> 999 possible
    return q;
}

// Persistent blocks; each iteration = 2 consecutive rows (threads 0-127 ->
// row 2rp via cols 2t,2t+1; threads 128-255 -> row 2rp+1), one bin set per
// half. Tagged bins ((iter<<8)|w, monotone -> no re-init). 16 KB, 2 barriers
// per iteration.
//
// Phase-split telescoping (all from atomicMax return values):
//   phase 1 (A): overtaking writer adds (w^2 - pv^2)      [stale tag -> 0]
//   barrier (A frozen)
//   phase 2 (B): overtaking writer reads frozen a_q once (LDS.32) and adds
//                (w^2 - pv^2) - 2*a_q*(w - pv)
// Chains telescope to a_q^2 + b_q^2 - 2 a_q b_q per bin = (a_q-b_q)^2,
// every bin counted exactly once, no post-pass.
__global__ __launch_bounds__(256, 8)
void holo_mse_kernel(const float* __restrict__ rec,
                     const float* __restrict__ tgt,
                     float* __restrict__ out)
{
    __shared__ int2 bins[2][TPAD];     // [row-half][bin]; .x=A tags, .y=B tags
    __shared__ float warp_sums[8];

    const int t    = threadIdx.x;
    const int half = t >> 7;
    const int w0   = (t & 127) * 2;
    const int w1   = w0 + 1;
    int2* __restrict__ bs = bins[half];

    #pragma unroll
    for (int i = t; i < 2 * TPAD; i += 256)
        bins[0][i] = make_int2(0, 0);
    __syncthreads();

    float acc = 0.0f;
    int iter = 1;

    int rp = blockIdx.x;
    float2 va = *(const float2*)(rec + (size_t)rp * 512 + 2 * t);
    float2 vb = *(const float2*)(tgt + (size_t)rp * 512 + 2 * t);

    for (; rp < ROWPAIRS; rp += GRID, ++iter) {
        const int hi   = iter << 8;
        const int tag0 = hi | w0;
        const int tag1 = hi | w1;

        const float2 bcur = vb;        // hold this iteration's B values
        int srow = 0;

        // ---- phase 1: A atomics ----
        if (va.x != 0.0f) {
            int q = quantize(va.x);
            int old = atomicMax(&bs[q].x, tag0);
            if (tag0 > old) {
                unsigned pw = (unsigned)(old - hi);
                int pv = (pw < 256u) ? (int)pw : 0;
                srow += w0 * w0 - pv * pv;
            }
        }
        if (va.y != 0.0f) {
            int q = quantize(va.y);
            int old = atomicMax(&bs[q].x, tag1);
            if (tag1 > old) {
                unsigned pw = (unsigned)(old - hi);
                int pv = (pw < 256u) ? (int)pw : 0;
                srow += w1 * w1 - pv * pv;
            }
        }

        // prefetch next iteration (overlaps barrier + phase 2)
        const int nrp = rp + GRID;
        if (nrp < ROWPAIRS) {
            va = *(const float2*)(rec + (size_t)nrp * 512 + 2 * t);
            vb = *(const float2*)(tgt + (size_t)nrp * 512 + 2 * t);
        }

        __syncthreads();               // A histogram frozen

        // ---- phase 2: B atomics + cross vs frozen A ----
        if (bcur.x != 0.0f) {
            int q = quantize(bcur.x);
            int old = atomicMax(&bs[q].y, tag0);
            if (tag0 > old) {
                unsigned pw = (unsigned)(old - hi);
                int pv = (pw < 256u) ? (int)pw : 0;
                unsigned da = (unsigned)(bs[q].x - hi);
                int aq = (da < 256u) ? (int)da : 0;
                srow += w0 * w0 - pv * pv - 2 * aq * (w0 - pv);
            }
        }
        if (bcur.y != 0.0f) {
            int q = quantize(bcur.y);
            int old = atomicMax(&bs[q].y, tag1);
            if (tag1 > old) {
                unsigned pw = (unsigned)(old - hi);
                int pv = (pw < 256u) ? (int)pw : 0;
                unsigned da = (unsigned)(bs[q].x - hi);
                int aq = (da < 256u) ? (int)da : 0;
                srow += w1 * w1 - pv * pv - 2 * aq * (w1 - pv);
            }
        }
        acc += (float)srow;            // |srow| < 2^21, ~7 iters: fp32-exact

        if (nrp < ROWPAIRS) __syncthreads();   // reads done before buffer reuse
    }

    // block reduction + single-kernel grid finalize
    #pragma unroll
    for (int off = 16; off > 0; off >>= 1)
        acc += __shfl_down_sync(0xffffffffu, acc, off);
    if ((t & 31) == 0) warp_sums[t >> 5] = acc;
    __syncthreads();
    if (t == 0) {
        float v = 0.0f;
        #pragma unroll
        for (int i = 0; i < 8; i++) v += warp_sums[i];
        atomicAdd(&g_partial, v);
        __threadfence();
        unsigned prev = atomicAdd(&g_count, 1u);
        if (prev == GRID - 1) {        // last block: publish + reset for replay
            __threadfence();
            float tot = *(volatile float*)&g_partial;
            out[0] = tot * (float)(1.0 / TOTAL_OUT);
            *(volatile float*)&g_partial = 0.0f;
            *(volatile unsigned*)&g_count = 0u;
        }
    }
}

extern "C" void kernel_launch(void* const* d_in, const int* in_sizes, int n_in,
                              void* d_out, int out_size)
{
    const float* rec = (const float*)d_in[0];
    const float* tgt = (const float*)d_in[1];
    float* out = (float*)d_out;

    holo_mse_kernel<<<GRID, 256>>>(rec, tgt, out);
}